// round 3
// baseline (speedup 1.0000x reference)
#include <cuda_runtime.h>
#include <cuda_bf16.h>

#define NB 16
#define NA 49104

// ---------------- scratch (device globals) ----------------
__device__ float g_score[NB * NA];
__device__ int   g_h1[NB * 4096];
__device__ int   g_h2[NB * 4096];
__device__ int   g_h3[NB * 256];
__device__ int   g_cnt[NB];
__device__ unsigned long long g_cand[NB * 1024];

__device__ float g_topScore[NB * 1024];
__device__ float g_topCls[NB * 1024];
__device__ float g_topTheta[NB * 1024];
__device__ float g_topBox[NB * 1024 * 4];

__device__ unsigned g_W[NB * 32 * 1024];  // [b][g][j] : bit i = iou(i=g*32+i, j)>thr && i<j
__device__ unsigned g_U[NB * 1024];       // [b][g*32+i] : intra-group row (suppressor i)

struct Ptrs { const float* p[20]; };

__device__ __forceinline__ void level_of(int a, int& l, int& p, int& h, int& s) {
    if (a < 36864)      { l = 0; p = a;         h = 192; s = 8;   }
    else if (a < 46080) { l = 1; p = a - 36864; h = 96;  s = 16;  }
    else if (a < 48384) { l = 2; p = a - 46080; h = 48;  s = 32;  }
    else if (a < 48960) { l = 3; p = a - 48384; h = 24;  s = 64;  }
    else                { l = 4; p = a - 48960; h = 12;  s = 128; }
}

// ---------------- kernel 0: zero state ----------------
__global__ void zero_kernel() {
    int t = blockIdx.x * blockDim.x + threadIdx.x;
    int n = blockDim.x * gridDim.x;
    for (int i = t; i < NB * 4096; i += n) { g_h1[i] = 0; g_h2[i] = 0; }
    for (int i = t; i < NB * 256; i += n) g_h3[i] = 0;
    if (t < NB) g_cnt[t] = 0;
}

// ---------------- kernel 1: scores + L1 histogram (12 top bits) ----------------
__global__ void __launch_bounds__(256) score_hist_kernel(Ptrs in) {
    __shared__ int hist[4096];
    int b = blockIdx.y, bx = blockIdx.x, tid = threadIdx.x;
    for (int i = tid; i < 4096; i += 256) hist[i] = 0;
    __syncthreads();

    int base = bx * 2048 + tid * 8;
    if (base < NA) {
#pragma unroll
        for (int q = 0; q < 2; q++) {
            int a0 = base + q * 4;
            int l, p, h, s; level_of(a0, l, p, h, s);
            int hh = h * h;
            const float4* cls = (const float4*)(in.p[l] + b * 15 * hh + p);
            int st = hh >> 2;
            float4 m4 = cls[0];
#pragma unroll
            for (int c = 1; c < 15; c++) {
                float4 v = cls[c * st];
                m4.x = fmaxf(m4.x, v.x); m4.y = fmaxf(m4.y, v.y);
                m4.z = fmaxf(m4.z, v.z); m4.w = fmaxf(m4.w, v.w);
            }
            float4 sc;
            sc.x = 1.0f / (1.0f + expf(-m4.x));
            sc.y = 1.0f / (1.0f + expf(-m4.y));
            sc.z = 1.0f / (1.0f + expf(-m4.z));
            sc.w = 1.0f / (1.0f + expf(-m4.w));
            *(float4*)&g_score[b * NA + a0] = sc;
            atomicAdd(&hist[__float_as_uint(sc.x) >> 20], 1);
            atomicAdd(&hist[__float_as_uint(sc.y) >> 20], 1);
            atomicAdd(&hist[__float_as_uint(sc.z) >> 20], 1);
            atomicAdd(&hist[__float_as_uint(sc.w) >> 20], 1);
        }
    }
    __syncthreads();
    for (int i = tid; i < 4096; i += 256) {
        int v = hist[i];
        if (v) atomicAdd(&g_h1[b * 4096 + i], v);
    }
}

// ---------------- per-block threshold selection from a global histogram ----------------
template<int NBINS>
__device__ __forceinline__ int select_bins(const int* gh, int target, int* sh, int* sres, int& accOut) {
    int tid = threadIdx.x, nt = blockDim.x;
    for (int i = tid; i < NBINS; i += nt) sh[i] = gh[i];
    __syncthreads();
    const int SEG = NBINS / 32;
    if (tid < 32) { int s = 0; for (int i = 0; i < SEG; i++) s += sh[tid * SEG + i]; sres[2 + tid] = s; }
    __syncthreads();
    if (tid == 0) {
        int acc = 0, T = 0;
        for (int seg = 31; seg >= 0; seg--) {
            int ps = sres[2 + seg];
            if (acc + ps >= target) {
                for (int bin = seg * SEG + SEG - 1;; bin--) {
                    int hc = sh[bin];
                    if (acc + hc >= target) { T = bin; break; }
                    acc += hc;
                }
                break;
            }
            acc += ps;
        }
        sres[0] = T; sres[1] = acc;
    }
    __syncthreads();
    accOut = sres[1];
    return sres[0];
}

// ---------------- kernel 2: compact bin>T1, histogram bin==T1 (mid 12 bits) ----------------
__global__ void __launch_bounds__(256) refine1_kernel() {
    __shared__ int sh[4096];
    __shared__ int sres[34];
    int b = blockIdx.y, bx = blockIdx.x, tid = threadIdx.x;
    int acc1;
    int T1 = select_bins<4096>(g_h1 + b * 4096, 1000, sh, sres, acc1);
    const float* sc = g_score + b * NA;
    int base = bx * 2048;
    for (int i = tid; i < 2048; i += 256) {
        int a = base + i;
        if (a >= NA) break;
        unsigned k = __float_as_uint(sc[a]);
        int bin = (int)(k >> 20);
        if (bin > T1) {
            int pos = atomicAdd(&g_cnt[b], 1);
            if (pos < 1024)
                g_cand[b * 1024 + pos] = ((unsigned long long)(~k) << 32) | (unsigned)a;
        } else if (bin == T1) {
            atomicAdd(&g_h2[b * 4096 + ((k >> 8) & 0xFFF)], 1);
        }
    }
}

// ---------------- kernel 3: compact mid>T2, histogram mid==T2 (low 8 bits) ----------------
__global__ void __launch_bounds__(256) refine2_kernel() {
    __shared__ int sh[4096];
    __shared__ int sres[34];
    int b = blockIdx.y, bx = blockIdx.x, tid = threadIdx.x;
    int acc1, acc2;
    int T1 = select_bins<4096>(g_h1 + b * 4096, 1000, sh, sres, acc1);
    int T2 = select_bins<4096>(g_h2 + b * 4096, 1000 - acc1, sh, sres, acc2);
    const float* sc = g_score + b * NA;
    int base = bx * 2048;
    for (int i = tid; i < 2048; i += 256) {
        int a = base + i;
        if (a >= NA) break;
        unsigned k = __float_as_uint(sc[a]);
        if ((int)(k >> 20) == T1) {
            int mid = (int)((k >> 8) & 0xFFF);
            if (mid > T2) {
                int pos = atomicAdd(&g_cnt[b], 1);
                if (pos < 1024)
                    g_cand[b * 1024 + pos] = ((unsigned long long)(~k) << 32) | (unsigned)a;
            } else if (mid == T2) {
                atomicAdd(&g_h3[b * 256 + (k & 0xFF)], 1);
            }
        }
    }
}

// ---------------- kernel 4: compact exact remainder ----------------
__global__ void __launch_bounds__(256) refine3_kernel() {
    __shared__ int sh[4096];
    __shared__ int sres[34];
    int b = blockIdx.y, bx = blockIdx.x, tid = threadIdx.x;
    int acc1, acc2, acc3;
    int T1 = select_bins<4096>(g_h1 + b * 4096, 1000, sh, sres, acc1);
    int T2 = select_bins<4096>(g_h2 + b * 4096, 1000 - acc1, sh, sres, acc2);
    int T3 = select_bins<256>(g_h3 + b * 256, 1000 - acc1 - acc2, sh, sres, acc3);
    unsigned pre24 = ((unsigned)T1 << 12) | (unsigned)T2;
    const float* sc = g_score + b * NA;
    int base = bx * 2048;
    for (int i = tid; i < 2048; i += 256) {
        int a = base + i;
        if (a >= NA) break;
        unsigned k = __float_as_uint(sc[a]);
        if ((k >> 8) == pre24 && (int)(k & 0xFF) >= T3) {
            int pos = atomicAdd(&g_cnt[b], 1);
            if (pos < 1024)
                g_cand[b * 1024 + pos] = ((unsigned long long)(~k) << 32) | (unsigned)a;
        }
    }
}

// ---------------- kernel 5: per-batch sort 1024 + winner decode ----------------
__global__ void __launch_bounds__(1024) sort_decode_kernel(Ptrs in) {
    __shared__ unsigned long long cand[1024];
    int b = blockIdx.x, tid = threadIdx.x;
    int c = min(g_cnt[b], 1024);
    cand[tid] = (tid < c) ? g_cand[b * 1024 + tid] : 0xFFFFFFFFFFFFFFFFULL;
    __syncthreads();

    // bitonic sort ascending (key = (~scorebits, idx))
    for (int k2 = 2; k2 <= 32; k2 <<= 1) {
        for (int s2 = k2 >> 1; s2 > 0; s2 >>= 1) {
            __syncwarp();
            int q = tid ^ s2;
            if (q > tid) {
                bool asc = ((tid & k2) == 0);
                unsigned long long A = cand[tid], Bv = cand[q];
                if ((A > Bv) == asc) { cand[tid] = Bv; cand[q] = A; }
            }
        }
    }
    for (int k2 = 64; k2 <= 1024; k2 <<= 1) {
        for (int s2 = k2 >> 1; s2 > 0; s2 >>= 1) {
            if (s2 >= 16) __syncthreads(); else __syncwarp();
            int q = tid ^ s2;
            if (q > tid) {
                bool asc = ((tid & k2) == 0);
                unsigned long long A = cand[tid], Bv = cand[q];
                if ((A > Bv) == asc) { cand[tid] = Bv; cand[q] = A; }
            }
        }
    }
    __syncthreads();

    int o = b * 1024 + tid;
    if (tid < 1000) {
        unsigned long long v = cand[tid];
        int a = (int)(unsigned)(v & 0xFFFFFFFFu);
        float score = __uint_as_float(~(unsigned)(v >> 32));

        int l, p, h, s; level_of(a, l, p, h, s);
        int hh = h * h;
        const float* cls = in.p[l]      + b * 15 * hh + p;
        const float* reg = in.p[5 + l]  + b * 5  * hh + p;
        const float* tcp = in.p[10 + l] + b * 18 * hh + p;
        const float* trp = in.p[15 + l] + b * hh + p;

        float best = cls[0]; int bc = 0;
#pragma unroll
        for (int cc = 1; cc < 15; cc++) { float vv = cls[cc * hh]; if (vv > best) { best = vv; bc = cc; } }
        float tb = tcp[0]; int ta = 0;
#pragma unroll
        for (int cc = 1; cc < 18; cc++) { float vv = tcp[cc * hh]; if (vv > tb) { tb = vv; ta = cc; } }
        float theta = (float)(ta + 1) * 10.0f + trp[0];

        float fs = (float)s;
        int col = p % h, row = p / h;
        float x = (float)col * fs + (float)(s / 2);
        float y = (float)row * fs + (float)(s / 2);

        g_topScore[o] = score;
        g_topCls[o]   = (float)(bc + 1);
        g_topTheta[o] = theta;
        g_topBox[o * 4 + 0] = x - reg[0] * fs;
        g_topBox[o * 4 + 1] = y - reg[hh] * fs;
        g_topBox[o * 4 + 2] = x + reg[2 * hh] * fs;
        g_topBox[o * 4 + 3] = y + reg[3 * hh] * fs;
    } else {
        g_topScore[o] = -1e30f;
        g_topCls[o] = 0.f; g_topTheta[o] = 0.f;
        g_topBox[o * 4 + 0] = 0.f; g_topBox[o * 4 + 1] = 0.f;
        g_topBox[o * 4 + 2] = 0.f; g_topBox[o * 4 + 3] = 0.f;
    }
}

// ---------------- kernel 6: IoU bit-masks (fully parallel) ----------------
__global__ void __launch_bounds__(1024) mask_kernel() {
    int b = blockIdx.y, g = blockIdx.x, j = threadIdx.x;
    __shared__ float ib[32][4];
    if (j < 32) {
#pragma unroll
        for (int k = 0; k < 4; k++) ib[j][k] = g_topBox[(b * 1024 + g * 32 + j) * 4 + k];
    }
    __syncthreads();

    float x1 = g_topBox[(b * 1024 + j) * 4 + 0];
    float y1 = g_topBox[(b * 1024 + j) * 4 + 1];
    float x2 = g_topBox[(b * 1024 + j) * 4 + 2];
    float y2 = g_topBox[(b * 1024 + j) * 4 + 3];
    float area = fmaxf(x2 - x1, 0.f) * fmaxf(y2 - y1, 0.f);

    unsigned w = 0;
#pragma unroll
    for (int bb = 0; bb < 32; bb++) {
        int i = g * 32 + bb;
        float ix1 = ib[bb][0], iy1 = ib[bb][1], ix2 = ib[bb][2], iy2 = ib[bb][3];
        float iarea = fmaxf(ix2 - ix1, 0.f) * fmaxf(iy2 - iy1, 0.f);
        float iw = fmaxf(fminf(x2, ix2) - fmaxf(x1, ix1), 0.f);
        float ih = fmaxf(fminf(y2, iy2) - fmaxf(y1, iy1), 0.f);
        float inter = iw * ih;
        float uni = fmaxf(area + iarea - inter, 1e-8f);
        bool pred = (inter > 0.3f * uni) && (i < j);
        w |= ((unsigned)pred) << bb;
    }
    g_W[(b * 32 + g) * 1024 + j] = w;

    if ((j >> 5) == g) {
        int lane = j & 31;
        unsigned u = 0;
#pragma unroll
        for (int i = 0; i < 32; i++) {
            unsigned t = __ballot_sync(0xffffffffu, (w >> i) & 1u);
            if (lane == i) u = t;
        }
        g_U[b * 1024 + g * 32 + lane] = u;
    }
}

// ---------------- kernel 7: barrier-free pipelined greedy scan + output ----------------
__global__ void __launch_bounds__(1024) scan_kernel(float* __restrict__ out) {
    int b = blockIdx.x, j = threadIdx.x;
    int lane = j & 31, wid = j >> 5;
    __shared__ unsigned su[1024];
    __shared__ unsigned long long sm64[32];

    float score = g_topScore[b * 1024 + j];
    bool alive = (j < 1000) && (score >= 0.05f);

    unsigned su_own = g_U[b * 1024 + j];
    su[j] = su_own;
    if (j < 32) sm64[j] = 0ULL;
    unsigned nzm = __ballot_sync(0xffffffffu, su_own != 0u);
    __syncthreads();

    const unsigned* Wb = g_W + b * 32 * 1024;
    for (int g = 0; g < wid; g++) {
        unsigned wv = Wb[g * 1024 + j];        // in flight during the spin below
        unsigned long long v;
        do { v = *(volatile const unsigned long long*)&sm64[g]; } while (!(v >> 32));
        unsigned mg = (unsigned)v;
        alive = alive && ((wv & mg) == 0u);
    }
    unsigned m = __ballot_sync(0xffffffffu, alive);
    if (lane == 0) {
        unsigned todo = nzm & m;
        while (todo) {
            int bb = __ffs(todo) - 1;
            m &= ~su[wid * 32 + bb];           // row bb has only bits > bb
            todo &= todo - 1;
            todo &= m;
        }
        *(volatile unsigned long long*)&sm64[wid] = (1ULL << 32) | (unsigned long long)m;
    }
    m = __shfl_sync(0xffffffffu, m, 0);
    alive = (m >> lane) & 1u;

    if (j < 1000) {
        float k = alive ? 1.0f : 0.0f;
        int o = b * 1024 + j;
        out[b * 1000 + j] = score * k;                          // scores_post
        out[16000 + b * 1000 + j] = k * g_topCls[o];            // classes_post
        int base = 32000 + (b * 1000 + j) * 5;
        out[base + 0] = k * g_topBox[o * 4 + 0];
        out[base + 1] = k * g_topBox[o * 4 + 1];
        out[base + 2] = k * g_topBox[o * 4 + 2];
        out[base + 3] = k * g_topBox[o * 4 + 3];
        out[base + 4] = k * g_topTheta[o];
    }
}

// ---------------- launch ----------------
extern "C" void kernel_launch(void* const* d_in, const int* in_sizes, int n_in,
                              void* d_out, int out_size) {
    Ptrs P;
    for (int i = 0; i < 20; i++) P.p[i] = (const float*)d_in[i];

    zero_kernel<<<64, 1024>>>();
    score_hist_kernel<<<dim3(24, NB), 256>>>(P);
    refine1_kernel<<<dim3(24, NB), 256>>>();
    refine2_kernel<<<dim3(24, NB), 256>>>();
    refine3_kernel<<<dim3(24, NB), 256>>>();
    sort_decode_kernel<<<NB, 1024>>>(P);
    mask_kernel<<<dim3(32, NB), 1024>>>();
    scan_kernel<<<NB, 1024>>>((float*)d_out);
}